// round 2
// baseline (speedup 1.0000x reference)
#include <cuda_runtime.h>
#include <math.h>

// Problem constants
#define Bc   256
#define Mc   196
#define Dc   512
#define TRIc 131328           // 512*513/2
#define TB   128              // output tile (TB x TB)
#define KC   28               // K chunk: 196 = 7*28 exactly
#define NPAIR 10              // upper-triangular pairs of 4 blocks

// Scratch (allocation-free rule: __device__ globals)
__device__ float g_diag[Bc * Dc];
__device__ float g_rowsum[Bc * Dc];
__device__ float g_tot[Bc];

__constant__ int c_bi[NPAIR] = {0,0,0,0,1,1,1,2,2,3};
__constant__ int c_bj[NPAIR] = {0,1,2,3,1,2,3,2,3,3};

// ---------------------------------------------------------------------------
// Kernel 1: diag[b,d] = sum_m x[b,m,d]^2 ; zero rowsum
// ---------------------------------------------------------------------------
__global__ void __launch_bounds__(512) diag_kernel(const float* __restrict__ x) {
    int b = blockIdx.x;
    int d = threadIdx.x;
    const float* xb = x + (size_t)b * Mc * Dc + d;
    float s = 0.f;
#pragma unroll 4
    for (int m = 0; m < Mc; ++m) {
        float v = xb[(size_t)m * Dc];
        s = fmaf(v, v, s);
    }
    g_diag[b * Dc + d]   = s;
    g_rowsum[b * Dc + d] = 0.f;
}

// ---------------------------------------------------------------------------
// Kernel 2: per (tile-pair, batch): 128x128 block of gram = X^T X,
// fused dcov/sqrt epilogue, triangle-packed store, row-sum accumulation.
// ---------------------------------------------------------------------------
__global__ void __launch_bounds__(256) gram_kernel(const float* __restrict__ x,
                                                   const float* __restrict__ t,
                                                   float* __restrict__ out) {
    __shared__ float As[KC][TB];
    __shared__ float Bs[KC][TB];
    __shared__ float rsum_i[TB];
    __shared__ float rsum_j[TB];

    const int b  = blockIdx.y;
    const int bi = c_bi[blockIdx.x];
    const int bj = c_bj[blockIdx.x];
    const int tid = threadIdx.x;
    const int tx = tid & 15;        // 16 col-groups of 8
    const int ty = tid >> 4;        // 16 row-groups of 8

    const float* xb = x + (size_t)b * Mc * Dc;

    float acc[8][8];
#pragma unroll
    for (int r = 0; r < 8; ++r)
#pragma unroll
        for (int c = 0; c < 8; ++c) acc[r][c] = 0.f;

    // K loop: 7 chunks of 28 (exact)
    for (int k0 = 0; k0 < Mc; k0 += KC) {
        // cooperative load: 28 rows x 128 cols for both column-blocks
        // 28*32 = 896 float4 slots per tile
#pragma unroll
        for (int l = 0; l < 4; ++l) {
            int idx = tid + l * 256;
            if (idx < KC * 32) {
                int k  = idx >> 5;
                int c4 = (idx & 31) << 2;
                const float* rowp = xb + (size_t)(k0 + k) * Dc;
                *(float4*)&As[k][c4] = *(const float4*)(rowp + bi * TB + c4);
                *(float4*)&Bs[k][c4] = *(const float4*)(rowp + bj * TB + c4);
            }
        }
        __syncthreads();

#pragma unroll 4
        for (int k = 0; k < KC; ++k) {
            float a[8], bb[8];
            *(float4*)&a[0]  = *(const float4*)&As[k][ty * 8];
            *(float4*)&a[4]  = *(const float4*)&As[k][ty * 8 + 4];
            *(float4*)&bb[0] = *(const float4*)&Bs[k][tx * 8];
            *(float4*)&bb[4] = *(const float4*)&Bs[k][tx * 8 + 4];
#pragma unroll
            for (int r = 0; r < 8; ++r)
#pragma unroll
                for (int c = 0; c < 8; ++c)
                    acc[r][c] = fmaf(a[r], bb[c], acc[r][c]);
        }
        __syncthreads();
    }

    // ---- epilogue ----
    if (tid < TB) { rsum_i[tid] = 0.f; rsum_j[tid] = 0.f; }
    __syncthreads();

    const float sc = expf(t[0]);
    const int i0 = bi * TB, j0 = bj * TB;
    const float* diag = &g_diag[b * Dc];
    float* outb = out + (size_t)b * TRIc;
    const bool diagBlk = (bi == bj);

    float colpart[8];
#pragma unroll
    for (int c = 0; c < 8; ++c) colpart[c] = 0.f;

#pragma unroll
    for (int r = 0; r < 8; ++r) {
        const int i = i0 + ty * 8 + r;
        const float di = diag[i];
        const int rowbase = (i * (2 * Dc - i + 1)) >> 1;  // elems before row i
        float rowpart = 0.f;
#pragma unroll
        for (int c = 0; c < 8; ++c) {
            const int j = j0 + tx * 8 + c;
            if (diagBlk && j < i) continue;   // lower half of diagonal tile
            float dv;
            if (i == j) {
                dv = 0.f;                      // exact, as in reference
            } else {
                dv = di + diag[j] - 2.f * acc[r][c];
                dv = fmaxf(dv, 0.f);
            }
            const float v = sqrtf(fmaf(sc, dv, 1e-5f));
            outb[rowbase + (j - i)] = v;
            rowpart += v;
            if (j > i) colpart[c] += v;        // symmetric mirror contribution
        }
        atomicAdd(&rsum_i[ty * 8 + r], rowpart);
    }
#pragma unroll
    for (int c = 0; c < 8; ++c) atomicAdd(&rsum_j[tx * 8 + c], colpart[c]);
    __syncthreads();

    if (tid < TB) {
        atomicAdd(&g_rowsum[b * Dc + i0 + tid], rsum_i[tid]);
        atomicAdd(&g_rowsum[b * Dc + j0 + tid], rsum_j[tid]);
    }
}

// ---------------------------------------------------------------------------
// Kernel 3: tot[b] = sum_d rowsum[b,d]
// ---------------------------------------------------------------------------
__global__ void __launch_bounds__(256) tot_kernel() {
    const int b = blockIdx.x;
    float s = 0.f;
    for (int d = threadIdx.x; d < Dc; d += 256) s += g_rowsum[b * Dc + d];
#pragma unroll
    for (int o = 16; o > 0; o >>= 1) s += __shfl_down_sync(0xffffffffu, s, o);
    __shared__ float red[8];
    if ((threadIdx.x & 31) == 0) red[threadIdx.x >> 5] = s;
    __syncthreads();
    if (threadIdx.x == 0) {
        float tt = 0.f;
#pragma unroll
        for (int w = 0; w < 8; ++w) tt += red[w];
        g_tot[b] = tt;
    }
}

// ---------------------------------------------------------------------------
// Kernel 4: in-place double centering over the packed triangle
// ---------------------------------------------------------------------------
__global__ void __launch_bounds__(256) center_kernel(float* __restrict__ out) {
    const int i = blockIdx.x;       // row 0..511
    const int b = blockIdx.y;
    const float* rs = &g_rowsum[b * Dc];
    const float inv  = 1.0f / (float)Dc;
    const float ri   = rs[i] * inv;
    const float totm = g_tot[b] * (inv * inv);
    float* row = out + (size_t)b * TRIc + ((i * (2 * Dc - i + 1)) >> 1);
    for (int j = i + threadIdx.x; j < Dc; j += 256) {
        row[j - i] = row[j - i] - ri - rs[j] * inv + totm;
    }
}

// ---------------------------------------------------------------------------
extern "C" void kernel_launch(void* const* d_in, const int* in_sizes, int n_in,
                              void* d_out, int out_size) {
    const float* x = (const float*)d_in[0];
    const float* t = (const float*)d_in[1];
    if (n_in >= 2 && in_sizes[0] == 1) {   // robustness vs metadata order
        x = (const float*)d_in[1];
        t = (const float*)d_in[0];
    }
    float* out = (float*)d_out;

    diag_kernel<<<Bc, 512>>>(x);
    gram_kernel<<<dim3(NPAIR, Bc), 256>>>(x, t, out);
    tot_kernel<<<Bc, 256>>>();
    center_kernel<<<dim3(Dc, Bc), 256>>>(out);
}

// round 3
// speedup vs baseline: 1.4381x; 1.4381x over previous
#include <cuda_runtime.h>
#include <cuda_bf16.h>
#include <math.h>
#include <stdint.h>

// Problem constants
#define Bc   256
#define Mc   196
#define Dc   512
#define TRIc 131328           // 512*513/2
#define TB   128              // output tile (TB x TB)
#define KC   32               // K chunk (196 padded to 224 = 7*32)
#define NCH  7
#define PITCH 136             // smem row pitch in bf16 halves (272B, 16B-aligned, ldmatrix conflict-free)
#define NPAIR 10              // upper-triangular pairs of 4 blocks

// Scratch (allocation-free rule: __device__ globals)
__device__ float g_diag[Bc * Dc];
__device__ float g_rowsum[Bc * Dc];
__device__ float g_tot[Bc];

__constant__ int c_bi[NPAIR] = {0,0,0,0,1,1,1,2,2,3};
__constant__ int c_bj[NPAIR] = {0,1,2,3,1,2,3,2,3,3};

// ---------------------------------------------------------------------------
// PTX helpers
// ---------------------------------------------------------------------------
__device__ __forceinline__ void ldm4t(uint32_t& r0, uint32_t& r1, uint32_t& r2,
                                      uint32_t& r3, uint32_t addr) {
    asm volatile("ldmatrix.sync.aligned.m8n8.x4.trans.shared.b16 {%0,%1,%2,%3}, [%4];"
                 : "=r"(r0), "=r"(r1), "=r"(r2), "=r"(r3) : "r"(addr));
}

__device__ __forceinline__ void mma_bf16(float* d, const uint32_t* a, const uint32_t* b) {
    asm volatile(
        "mma.sync.aligned.m16n8k16.row.col.f32.bf16.bf16.f32 "
        "{%0,%1,%2,%3}, {%4,%5,%6,%7}, {%8,%9}, {%0,%1,%2,%3};"
        : "+f"(d[0]), "+f"(d[1]), "+f"(d[2]), "+f"(d[3])
        : "r"(a[0]), "r"(a[1]), "r"(a[2]), "r"(a[3]), "r"(b[0]), "r"(b[1]));
}

// Fragment base address for an (k0, c0) 16x16 block in a [k][col] bf16 tile.
// lanes 0-7: rows k0+r, col c0; 8-15: k0+r, c0+8; 16-23: k0+8+r, c0; 24-31: k0+8+r, c0+8
__device__ __forceinline__ uint32_t frag_addr(uint32_t base, int k0, int c0, int lane) {
    int g = lane >> 3, r = lane & 7;
    int k = k0 + r + ((g >> 1) << 3);
    int c = c0 + ((g & 1) << 3);
    return base + (uint32_t)(k * (PITCH * 2) + c * 2);
}

// ---------------------------------------------------------------------------
// Kernel 1: diag[b,d] = sum_m x[b,m,d]^2 ; zero rowsum   (fp32, exact)
// ---------------------------------------------------------------------------
__global__ void __launch_bounds__(512) diag_kernel(const float* __restrict__ x) {
    int b = blockIdx.x;
    int d = threadIdx.x;
    const float* xb = x + (size_t)b * Mc * Dc + d;
    float s = 0.f;
#pragma unroll 4
    for (int m = 0; m < Mc; ++m) {
        float v = xb[(size_t)m * Dc];
        s = fmaf(v, v, s);
    }
    g_diag[b * Dc + d]   = s;
    g_rowsum[b * Dc + d] = 0.f;
}

// ---------------------------------------------------------------------------
// Kernel 2: 128x128 gram tile via bf16-split mma.sync + fused dcov/sqrt
// epilogue, triangle-packed store, row-sum accumulation.
// 256 threads = 8 warps; warp tile 32(M) x 64(N): wm = wid&3, wn = wid>>2.
// ---------------------------------------------------------------------------
__global__ void __launch_bounds__(256, 2) gram_kernel(const float* __restrict__ x,
                                                      const float* __restrict__ t,
                                                      float* __restrict__ out) {
    __shared__ __align__(256) __nv_bfloat16 sAhi[KC][PITCH];
    __shared__ __align__(256) __nv_bfloat16 sAlo[KC][PITCH];
    __shared__ __align__(256) __nv_bfloat16 sBhi[KC][PITCH];
    __shared__ __align__(256) __nv_bfloat16 sBlo[KC][PITCH];
    __shared__ float rsum_i[TB];
    __shared__ float rsum_j[TB];

    const int b   = blockIdx.y;
    const int bi  = c_bi[blockIdx.x];
    const int bj  = c_bj[blockIdx.x];
    const int tid = threadIdx.x;
    const int lane = tid & 31;
    const int wid  = tid >> 5;
    const int wm   = wid & 3;   // 4 M-groups of 32 rows
    const int wn   = wid >> 2;  // 2 N-groups of 64 cols

    const float* xb = x + (size_t)b * Mc * Dc;

    const uint32_t aHiB = (uint32_t)__cvta_generic_to_shared(&sAhi[0][0]);
    const uint32_t aLoB = (uint32_t)__cvta_generic_to_shared(&sAlo[0][0]);
    const uint32_t bHiB = (uint32_t)__cvta_generic_to_shared(&sBhi[0][0]);
    const uint32_t bLoB = (uint32_t)__cvta_generic_to_shared(&sBlo[0][0]);

    float acc[2][8][4];
#pragma unroll
    for (int mt = 0; mt < 2; ++mt)
#pragma unroll
        for (int nt = 0; nt < 8; ++nt)
#pragma unroll
            for (int v = 0; v < 4; ++v) acc[mt][nt][v] = 0.f;

    for (int ch = 0; ch < NCH; ++ch) {
        const int k0c = ch * KC;
        __syncthreads();
        // Load fp32, split into hi/lo bf16, store [k][col] (n-contiguous).
        // 32 rows x 32 float4 per tile; 256 threads -> 4 slots/thread/tile.
#pragma unroll
        for (int it = 0; it < 4; ++it) {
            int slot = tid + it * 256;
            int k  = slot >> 5;
            int c4 = (slot & 31) << 2;
            int kg = k0c + k;
            float4 va = make_float4(0.f, 0.f, 0.f, 0.f);
            float4 vb = make_float4(0.f, 0.f, 0.f, 0.f);
            if (kg < Mc) {
                const float* rowp = xb + (size_t)kg * Dc;
                va = *(const float4*)(rowp + bi * TB + c4);
                vb = *(const float4*)(rowp + bj * TB + c4);
            }
            __nv_bfloat16 hx, hy, hz, hw;
            // A tile
            hx = __float2bfloat16(va.x); hy = __float2bfloat16(va.y);
            hz = __float2bfloat16(va.z); hw = __float2bfloat16(va.w);
            {
                __nv_bfloat162 h0 = __nv_bfloat162(hx, hy), h1 = __nv_bfloat162(hz, hw);
                __nv_bfloat162 l0 = __nv_bfloat162(__float2bfloat16(va.x - __bfloat162float(hx)),
                                                   __float2bfloat16(va.y - __bfloat162float(hy)));
                __nv_bfloat162 l1 = __nv_bfloat162(__float2bfloat16(va.z - __bfloat162float(hz)),
                                                   __float2bfloat16(va.w - __bfloat162float(hw)));
                *(__nv_bfloat162*)&sAhi[k][c4]     = h0;
                *(__nv_bfloat162*)&sAhi[k][c4 + 2] = h1;
                *(__nv_bfloat162*)&sAlo[k][c4]     = l0;
                *(__nv_bfloat162*)&sAlo[k][c4 + 2] = l1;
            }
            // B tile
            hx = __float2bfloat16(vb.x); hy = __float2bfloat16(vb.y);
            hz = __float2bfloat16(vb.z); hw = __float2bfloat16(vb.w);
            {
                __nv_bfloat162 h0 = __nv_bfloat162(hx, hy), h1 = __nv_bfloat162(hz, hw);
                __nv_bfloat162 l0 = __nv_bfloat162(__float2bfloat16(vb.x - __bfloat162float(hx)),
                                                   __float2bfloat16(vb.y - __bfloat162float(hy)));
                __nv_bfloat162 l1 = __nv_bfloat162(__float2bfloat16(vb.z - __bfloat162float(hz)),
                                                   __float2bfloat16(vb.w - __bfloat162float(hw)));
                *(__nv_bfloat162*)&sBhi[k][c4]     = h0;
                *(__nv_bfloat162*)&sBhi[k][c4 + 2] = h1;
                *(__nv_bfloat162*)&sBlo[k][c4]     = l0;
                *(__nv_bfloat162*)&sBlo[k][c4 + 2] = l1;
            }
        }
        __syncthreads();

        // 2 k-steps of 16
#pragma unroll
        for (int ks = 0; ks < 2; ++ks) {
            const int k0 = ks * 16;
            uint32_t aF[2][4], bF[4][4];
            // pass 1: hi * hi
#pragma unroll
            for (int mt = 0; mt < 2; ++mt)
                ldm4t(aF[mt][0], aF[mt][1], aF[mt][2], aF[mt][3],
                      frag_addr(aHiB, k0, wm * 32 + mt * 16, lane));
#pragma unroll
            for (int np = 0; np < 4; ++np)
                ldm4t(bF[np][0], bF[np][1], bF[np][2], bF[np][3],
                      frag_addr(bHiB, k0, wn * 64 + np * 16, lane));
#pragma unroll
            for (int mt = 0; mt < 2; ++mt)
#pragma unroll
                for (int nt = 0; nt < 8; ++nt) {
                    uint32_t bb[2] = { bF[nt >> 1][nt & 1], bF[nt >> 1][2 + (nt & 1)] };
                    mma_bf16(acc[mt][nt], aF[mt], bb);
                }
            // pass 2: lo * hi
#pragma unroll
            for (int mt = 0; mt < 2; ++mt)
                ldm4t(aF[mt][0], aF[mt][1], aF[mt][2], aF[mt][3],
                      frag_addr(aLoB, k0, wm * 32 + mt * 16, lane));
#pragma unroll
            for (int mt = 0; mt < 2; ++mt)
#pragma unroll
                for (int nt = 0; nt < 8; ++nt) {
                    uint32_t bb[2] = { bF[nt >> 1][nt & 1], bF[nt >> 1][2 + (nt & 1)] };
                    mma_bf16(acc[mt][nt], aF[mt], bb);
                }
            // pass 3: hi * lo
#pragma unroll
            for (int np = 0; np < 4; ++np)
                ldm4t(bF[np][0], bF[np][1], bF[np][2], bF[np][3],
                      frag_addr(bLoB, k0, wn * 64 + np * 16, lane));
#pragma unroll
            for (int mt = 0; mt < 2; ++mt)
                ldm4t(aF[mt][0], aF[mt][1], aF[mt][2], aF[mt][3],
                      frag_addr(aHiB, k0, wm * 32 + mt * 16, lane));
#pragma unroll
            for (int mt = 0; mt < 2; ++mt)
#pragma unroll
                for (int nt = 0; nt < 8; ++nt) {
                    uint32_t bb[2] = { bF[nt >> 1][nt & 1], bF[nt >> 1][2 + (nt & 1)] };
                    mma_bf16(acc[mt][nt], aF[mt], bb);
                }
        }
    }

    // ---- epilogue ----
    __syncthreads();
    if (tid < TB) { rsum_i[tid] = 0.f; rsum_j[tid] = 0.f; }
    __syncthreads();

    const float sc = expf(t[0]);
    const int i0 = bi * TB, j0 = bj * TB;
    const float* diag = &g_diag[b * Dc];
    float* outb = out + (size_t)b * TRIc;
    const bool diagBlk = (bi == bj);

    float colpart[16];
#pragma unroll
    for (int c = 0; c < 16; ++c) colpart[c] = 0.f;

#pragma unroll
    for (int mt = 0; mt < 2; ++mt) {
#pragma unroll
        for (int vr = 0; vr < 2; ++vr) {
            const int lr = wm * 32 + mt * 16 + (lane >> 2) + vr * 8;
            const int i = i0 + lr;
            const float di = diag[i];
            const int rowbase = (i * (2 * Dc - i + 1)) >> 1;
            float rowpart = 0.f;
#pragma unroll
            for (int nt = 0; nt < 8; ++nt) {
#pragma unroll
                for (int bb2 = 0; bb2 < 2; ++bb2) {
                    const int lc = wn * 64 + nt * 8 + ((lane & 3) << 1) + bb2;
                    const int j = j0 + lc;
                    if (diagBlk && j < i) continue;
                    float dv;
                    if (i == j) {
                        dv = 0.f;
                    } else {
                        dv = di + diag[j] - 2.f * acc[mt][nt][vr * 2 + bb2];
                        dv = fmaxf(dv, 0.f);
                    }
                    const float v = sqrtf(fmaf(sc, dv, 1e-5f));
                    outb[rowbase + (j - i)] = v;
                    rowpart += v;
                    if (j > i) colpart[nt * 2 + bb2] += v;
                }
            }
            atomicAdd(&rsum_i[lr], rowpart);
        }
    }
#pragma unroll
    for (int nt = 0; nt < 8; ++nt)
#pragma unroll
        for (int bb2 = 0; bb2 < 2; ++bb2) {
            const int lc = wn * 64 + nt * 8 + ((lane & 3) << 1) + bb2;
            atomicAdd(&rsum_j[lc], colpart[nt * 2 + bb2]);
        }
    __syncthreads();

    if (tid < TB) {
        atomicAdd(&g_rowsum[b * Dc + i0 + tid], rsum_i[tid]);
        atomicAdd(&g_rowsum[b * Dc + j0 + tid], rsum_j[tid]);
    }
}

// ---------------------------------------------------------------------------
// Kernel 3: tot[b] = sum_d rowsum[b,d]
// ---------------------------------------------------------------------------
__global__ void __launch_bounds__(256) tot_kernel() {
    const int b = blockIdx.x;
    float s = 0.f;
    for (int d = threadIdx.x; d < Dc; d += 256) s += g_rowsum[b * Dc + d];
#pragma unroll
    for (int o = 16; o > 0; o >>= 1) s += __shfl_down_sync(0xffffffffu, s, o);
    __shared__ float red[8];
    if ((threadIdx.x & 31) == 0) red[threadIdx.x >> 5] = s;
    __syncthreads();
    if (threadIdx.x == 0) {
        float tt = 0.f;
#pragma unroll
        for (int w = 0; w < 8; ++w) tt += red[w];
        g_tot[b] = tt;
    }
}

// ---------------------------------------------------------------------------
// Kernel 4: in-place double centering; balanced mirrored row pairs.
// block = (g, b): rows {4g+u} and {511-(4g+u)} for u in 0..3  (8 rows, ~2052 elems)
// ---------------------------------------------------------------------------
__global__ void __launch_bounds__(256) center_kernel(float* __restrict__ out) {
    __shared__ float rsn[Dc];
    const int g = blockIdx.x;     // 0..63
    const int b = blockIdx.y;
    const float inv = 1.0f / (float)Dc;
    const float* rs = &g_rowsum[b * Dc];
#pragma unroll
    for (int u = 0; u < 2; ++u)
        rsn[threadIdx.x + u * 256] = rs[threadIdx.x + u * 256] * inv;
    __syncthreads();
    const float totm = g_tot[b] * (inv * inv);
    float* outb = out + (size_t)b * TRIc;

#pragma unroll
    for (int u = 0; u < 4; ++u) {
        const int ia = g * 4 + u;        // 0..255
        const int ib2 = (Dc - 1) - ia;   // 256..511
#pragma unroll
        for (int s = 0; s < 2; ++s) {
            const int i = s ? ib2 : ia;
            const float ri = rsn[i];
            const float add = totm - ri;
            float* row = outb + ((i * (2 * Dc - i + 1)) >> 1);
            const int len = Dc - i;
            for (int jj = threadIdx.x; jj < len; jj += 256) {
                row[jj] = row[jj] + add - rsn[i + jj];
            }
        }
    }
}

// ---------------------------------------------------------------------------
extern "C" void kernel_launch(void* const* d_in, const int* in_sizes, int n_in,
                              void* d_out, int out_size) {
    const float* x = (const float*)d_in[0];
    const float* t = (const float*)d_in[1];
    if (n_in >= 2 && in_sizes[0] == 1) {   // robustness vs metadata order
        x = (const float*)d_in[1];
        t = (const float*)d_in[0];
    }
    float* out = (float*)d_out;

    diag_kernel<<<Bc, 512>>>(x);
    gram_kernel<<<dim3(NPAIR, Bc), 256>>>(x, t, out);
    tot_kernel<<<Bc, 256>>>();
    center_kernel<<<dim3(64, Bc), 256>>>(out);
}

// round 9
// speedup vs baseline: 1.5484x; 1.0767x over previous
#include <cuda_runtime.h>
#include <cuda_bf16.h>
#include <math.h>
#include <stdint.h>

// Problem constants
#define Bc   256
#define Mc   196
#define Dc   512
#define TRIc 131328           // 512*513/2
#define TB   128              // output tile (TB x TB)
#define KC   16               // K chunk rows (196 padded to 208 = 13*16)
#define NCH  13
#define PITCH 136             // smem row pitch in bf16 halves (272B)
#define TILEB (KC * PITCH * 2)   // 4352 bytes per tile
#define STAGEB (4 * TILEB)       // Ahi,Alo,Bhi,Blo = 17408
#define NPAIR 10

// Scratch (allocation-free rule: __device__ globals)
__device__ float g_diag[Bc * Dc];
__device__ float g_rowsum[Bc * Dc];
__device__ float g_tot[Bc];
__device__ __nv_bfloat16 g_xhi[(size_t)Bc * Mc * Dc];
__device__ __nv_bfloat16 g_xlo[(size_t)Bc * Mc * Dc];

__constant__ int c_bi[NPAIR] = {0,0,0,0,1,1,1,2,2,3};
__constant__ int c_bj[NPAIR] = {0,1,2,3,1,2,3,2,3,3};

// ---------------------------------------------------------------------------
// PTX helpers (base PTX only: ldmatrix / mma.sync / cp.async — sm_103-safe)
// ---------------------------------------------------------------------------
__device__ __forceinline__ void ldm4t(uint32_t& r0, uint32_t& r1, uint32_t& r2,
                                      uint32_t& r3, uint32_t addr) {
    asm volatile("ldmatrix.sync.aligned.m8n8.x4.trans.shared.b16 {%0,%1,%2,%3}, [%4];"
                 : "=r"(r0), "=r"(r1), "=r"(r2), "=r"(r3) : "r"(addr));
}

__device__ __forceinline__ void mma_bf16(float* d, const uint32_t* a, const uint32_t* b) {
    asm volatile(
        "mma.sync.aligned.m16n8k16.row.col.f32.bf16.bf16.f32 "
        "{%0,%1,%2,%3}, {%4,%5,%6,%7}, {%8,%9}, {%0,%1,%2,%3};"
        : "+f"(d[0]), "+f"(d[1]), "+f"(d[2]), "+f"(d[3])
        : "r"(a[0]), "r"(a[1]), "r"(a[2]), "r"(a[3]), "r"(b[0]), "r"(b[1]));
}

__device__ __forceinline__ void cp16(uint32_t saddr, const void* gaddr, uint32_t srcsz) {
    asm volatile("cp.async.ca.shared.global [%0], [%1], 16, %2;"
                 :: "r"(saddr), "l"(gaddr), "r"(srcsz) : "memory");
}
__device__ __forceinline__ void cp_commit() {
    asm volatile("cp.async.commit_group;" ::: "memory");
}
template<int N>
__device__ __forceinline__ void cp_wait() {
    asm volatile("cp.async.wait_group %0;" :: "n"(N) : "memory");
}

// Fragment base address for a (0, c0) 16x16 block in a [k][col] bf16 tile.
__device__ __forceinline__ uint32_t frag_addr(uint32_t base, int c0, int lane) {
    int g = lane >> 3, r = lane & 7;
    int k = r + ((g >> 1) << 3);
    int c = c0 + ((g & 1) << 3);
    return base + (uint32_t)(k * (PITCH * 2) + c * 2);
}

// ---------------------------------------------------------------------------
// Kernel 0: fp32 -> bf16 hi/lo split (streamed once)
// ---------------------------------------------------------------------------
__global__ void __launch_bounds__(256) split_kernel(const float* __restrict__ x) {
    const size_t idx = (size_t)blockIdx.x * 256 + threadIdx.x;   // float4 index
    const float4 v = ((const float4*)x)[idx];
    __nv_bfloat16 h0 = __float2bfloat16(v.x), h1 = __float2bfloat16(v.y);
    __nv_bfloat16 h2 = __float2bfloat16(v.z), h3 = __float2bfloat16(v.w);
    __nv_bfloat162 hA(h0, h1), hB(h2, h3);
    __nv_bfloat162 lA(__float2bfloat16(v.x - __bfloat162float(h0)),
                      __float2bfloat16(v.y - __bfloat162float(h1)));
    __nv_bfloat162 lB(__float2bfloat16(v.z - __bfloat162float(h2)),
                      __float2bfloat16(v.w - __bfloat162float(h3)));
    uint2 uh, ul;
    uh.x = *(uint32_t*)&hA; uh.y = *(uint32_t*)&hB;
    ul.x = *(uint32_t*)&lA; ul.y = *(uint32_t*)&lB;
    *(uint2*)(g_xhi + idx * 4) = uh;
    *(uint2*)(g_xlo + idx * 4) = ul;
}

// ---------------------------------------------------------------------------
// Kernel 1: diag[b,d] = sum_m x[b,m,d]^2 ; zero rowsum   (fp32, exact)
// ---------------------------------------------------------------------------
__global__ void __launch_bounds__(512) diag_kernel(const float* __restrict__ x) {
    int b = blockIdx.x;
    int d = threadIdx.x;
    const float* xb = x + (size_t)b * Mc * Dc + d;
    float s = 0.f;
#pragma unroll 4
    for (int m = 0; m < Mc; ++m) {
        float v = xb[(size_t)m * Dc];
        s = fmaf(v, v, s);
    }
    g_diag[b * Dc + d]   = s;
    g_rowsum[b * Dc + d] = 0.f;
}

// ---------------------------------------------------------------------------
// Kernel 2: 128x128 gram tile, bf16-split mma.sync, cp.async double-buffered.
// 256 threads = 8 warps; warp tile 32(M) x 64(N).
// STATIC smem: 2 stages x [Ahi|Alo|Bhi|Blo] (16 x 272B each) + rsum_i/j
// = 35840 B < 48KB (no cudaFuncSetAttribute needed).
// ---------------------------------------------------------------------------
__global__ void __launch_bounds__(256, 2) gram_kernel(const float* __restrict__ t,
                                                      float* __restrict__ out) {
    __shared__ __align__(16) char smem[2 * STAGEB];
    __shared__ float rsum_i[TB];
    __shared__ float rsum_j[TB];
    const uint32_t sbase = (uint32_t)__cvta_generic_to_shared(smem);

    const int b   = blockIdx.y;
    const int bi  = c_bi[blockIdx.x];
    const int bj  = c_bj[blockIdx.x];
    const int tid = threadIdx.x;
    const int lane = tid & 31;
    const int wid  = tid >> 5;
    const int wm   = wid & 3;
    const int wn   = wid >> 2;

    // cp.async slot mapping: 1024 16B-chunks per stage over 256 threads (4 ea)
    // slot -> tile(2b) | row(4b) | c16(4b)
    const size_t rowbase_g = (size_t)b * Mc * Dc;

    auto issue_chunk = [&](int ch, int st) {
        const uint32_t stb = sbase + st * STAGEB;
        const int k0c = ch * KC;
#pragma unroll
        for (int it = 0; it < 4; ++it) {
            const int slot = tid + it * 256;
            const int tile = slot >> 8;
            const int r    = (slot >> 4) & 15;
            const int c16  = slot & 15;
            const int kg   = k0c + r;
            const int kcl  = (kg < Mc) ? kg : 0;
            const uint32_t srcsz = (kg < Mc) ? 16u : 0u;
            const __nv_bfloat16* src =
                ((tile & 1) ? g_xlo : g_xhi) + rowbase_g + (size_t)kcl * Dc
                + ((tile >> 1) ? bj : bi) * TB + c16 * 8;
            cp16(stb + tile * TILEB + r * (PITCH * 2) + c16 * 16, src, srcsz);
        }
        cp_commit();
    };

    if (tid < TB) { rsum_i[tid] = 0.f; rsum_j[tid] = 0.f; }

    float acc[2][8][4];
#pragma unroll
    for (int mt = 0; mt < 2; ++mt)
#pragma unroll
        for (int nt = 0; nt < 8; ++nt)
#pragma unroll
            for (int v = 0; v < 4; ++v) acc[mt][nt][v] = 0.f;

    issue_chunk(0, 0);

    for (int ch = 0; ch < NCH; ++ch) {
        if (ch + 1 < NCH) {
            issue_chunk(ch + 1, (ch + 1) & 1);
            cp_wait<1>();
        } else {
            cp_wait<0>();
        }
        __syncthreads();

        const uint32_t stb = sbase + (ch & 1) * STAGEB;
        const uint32_t aHiB = stb, aLoB = stb + TILEB;
        const uint32_t bHiB = stb + 2 * TILEB, bLoB = stb + 3 * TILEB;

        uint32_t aHi[2][4], aLo[2][4], bF[4][4];
        // pass 1: hi * hi  (A-hi fragments stay register-resident)
#pragma unroll
        for (int mt = 0; mt < 2; ++mt)
            ldm4t(aHi[mt][0], aHi[mt][1], aHi[mt][2], aHi[mt][3],
                  frag_addr(aHiB, wm * 32 + mt * 16, lane));
#pragma unroll
        for (int np = 0; np < 4; ++np)
            ldm4t(bF[np][0], bF[np][1], bF[np][2], bF[np][3],
                  frag_addr(bHiB, wn * 64 + np * 16, lane));
#pragma unroll
        for (int mt = 0; mt < 2; ++mt)
#pragma unroll
            for (int nt = 0; nt < 8; ++nt) {
                uint32_t bb[2] = { bF[nt >> 1][nt & 1], bF[nt >> 1][2 + (nt & 1)] };
                mma_bf16(acc[mt][nt], aHi[mt], bb);
            }
        // pass 2: lo * hi
#pragma unroll
        for (int mt = 0; mt < 2; ++mt)
            ldm4t(aLo[mt][0], aLo[mt][1], aLo[mt][2], aLo[mt][3],
                  frag_addr(aLoB, wm * 32 + mt * 16, lane));
#pragma unroll
        for (int mt = 0; mt < 2; ++mt)
#pragma unroll
            for (int nt = 0; nt < 8; ++nt) {
                uint32_t bb[2] = { bF[nt >> 1][nt & 1], bF[nt >> 1][2 + (nt & 1)] };
                mma_bf16(acc[mt][nt], aLo[mt], bb);
            }
        // pass 3: hi * lo  (A-hi reused from registers — no reload)
#pragma unroll
        for (int np = 0; np < 4; ++np)
            ldm4t(bF[np][0], bF[np][1], bF[np][2], bF[np][3],
                  frag_addr(bLoB, wn * 64 + np * 16, lane));
#pragma unroll
        for (int mt = 0; mt < 2; ++mt)
#pragma unroll
            for (int nt = 0; nt < 8; ++nt) {
                uint32_t bb[2] = { bF[nt >> 1][nt & 1], bF[nt >> 1][2 + (nt & 1)] };
                mma_bf16(acc[mt][nt], aHi[mt], bb);
            }

        __syncthreads();   // stage consumed; safe for next issue to overwrite
    }

    // ---- epilogue ----
    const float sc = expf(t[0]);
    const int i0 = bi * TB, j0 = bj * TB;
    const float* diag = &g_diag[b * Dc];
    float* outb = out + (size_t)b * TRIc;
    const bool diagBlk = (bi == bj);

    float colpart[16];
#pragma unroll
    for (int c = 0; c < 16; ++c) colpart[c] = 0.f;

#pragma unroll
    for (int mt = 0; mt < 2; ++mt) {
#pragma unroll
        for (int vr = 0; vr < 2; ++vr) {
            const int lr = wm * 32 + mt * 16 + (lane >> 2) + vr * 8;
            const int i = i0 + lr;
            const float di = diag[i];
            const int rowbase = (i * (2 * Dc - i + 1)) >> 1;
            float rowpart = 0.f;
#pragma unroll
            for (int nt = 0; nt < 8; ++nt) {
#pragma unroll
                for (int bb2 = 0; bb2 < 2; ++bb2) {
                    const int lc = wn * 64 + nt * 8 + ((lane & 3) << 1) + bb2;
                    const int j = j0 + lc;
                    if (diagBlk && j < i) continue;
                    float dv;
                    if (i == j) {
                        dv = 0.f;
                    } else {
                        dv = di + diag[j] - 2.f * acc[mt][nt][vr * 2 + bb2];
                        dv = fmaxf(dv, 0.f);
                    }
                    const float v = sqrtf(fmaf(sc, dv, 1e-5f));
                    outb[rowbase + (j - i)] = v;
                    rowpart += v;
                    if (j > i) colpart[nt * 2 + bb2] += v;
                }
            }
            atomicAdd(&rsum_i[lr], rowpart);
        }
    }
#pragma unroll
    for (int nt = 0; nt < 8; ++nt)
#pragma unroll
        for (int bb2 = 0; bb2 < 2; ++bb2) {
            const int lc = wn * 64 + nt * 8 + ((lane & 3) << 1) + bb2;
            atomicAdd(&rsum_j[lc], colpart[nt * 2 + bb2]);
        }
    __syncthreads();

    if (tid < TB) {
        atomicAdd(&g_rowsum[b * Dc + i0 + tid], rsum_i[tid]);
        atomicAdd(&g_rowsum[b * Dc + j0 + tid], rsum_j[tid]);
    }
}

// ---------------------------------------------------------------------------
// Kernel 3: tot[b] = sum_d rowsum[b,d]
// ---------------------------------------------------------------------------
__global__ void __launch_bounds__(256) tot_kernel() {
    const int b = blockIdx.x;
    float s = 0.f;
    for (int d = threadIdx.x; d < Dc; d += 256) s += g_rowsum[b * Dc + d];
#pragma unroll
    for (int o = 16; o > 0; o >>= 1) s += __shfl_down_sync(0xffffffffu, s, o);
    __shared__ float red[8];
    if ((threadIdx.x & 31) == 0) red[threadIdx.x >> 5] = s;
    __syncthreads();
    if (threadIdx.x == 0) {
        float tt = 0.f;
#pragma unroll
        for (int w = 0; w < 8; ++w) tt += red[w];
        g_tot[b] = tt;
    }
}

// ---------------------------------------------------------------------------
// Kernel 4: in-place double centering; mirrored row pairs; float4 body.
// ---------------------------------------------------------------------------
__global__ void __launch_bounds__(256) center_kernel(float* __restrict__ out) {
    __shared__ float rsn[Dc];
    const int g = blockIdx.x;     // 0..63
    const int b = blockIdx.y;
    const float inv = 1.0f / (float)Dc;
    const float* rs = &g_rowsum[b * Dc];
#pragma unroll
    for (int u = 0; u < 2; ++u)
        rsn[threadIdx.x + u * 256] = rs[threadIdx.x + u * 256] * inv;
    __syncthreads();
    const float totm = g_tot[b] * (inv * inv);
    float* outb = out + (size_t)b * TRIc;

#pragma unroll
    for (int u = 0; u < 4; ++u) {
        const int ia  = g * 4 + u;
        const int ib2 = (Dc - 1) - ia;
#pragma unroll
        for (int s = 0; s < 2; ++s) {
            const int i = s ? ib2 : ia;
            const float add = totm - rsn[i];
            const int rowbase = (i * (2 * Dc - i + 1)) >> 1;
            float* row = outb + rowbase;
            const int len = Dc - i;
            int start = (4 - (rowbase & 3)) & 3;
            if (start > len) start = len;
            // scalar head
            if (threadIdx.x < (unsigned)start) {
                int jj = threadIdx.x;
                row[jj] += add - rsn[i + jj];
            }
            const int nv4 = (len - start) >> 2;
            float4* p4 = (float4*)(row + start);
            const float* rb = &rsn[i + start];
            for (int q = threadIdx.x; q < nv4; q += 256) {
                float4 v = p4[q];
                const int o4 = q * 4;
                v.x += add - rb[o4];
                v.y += add - rb[o4 + 1];
                v.z += add - rb[o4 + 2];
                v.w += add - rb[o4 + 3];
                p4[q] = v;
            }
            // scalar tail
            const int tail0 = start + nv4 * 4;
            for (int jj = tail0 + threadIdx.x; jj < len; jj += 256) {
                row[jj] += add - rsn[i + jj];
            }
        }
    }
}

// ---------------------------------------------------------------------------
extern "C" void kernel_launch(void* const* d_in, const int* in_sizes, int n_in,
                              void* d_out, int out_size) {
    const float* x = (const float*)d_in[0];
    const float* t = (const float*)d_in[1];
    if (n_in >= 2 && in_sizes[0] == 1) {
        x = (const float*)d_in[1];
        t = (const float*)d_in[0];
    }
    float* out = (float*)d_out;

    split_kernel<<<(Bc * Mc * Dc) / (256 * 4), 256>>>(x);
    diag_kernel<<<Bc, 512>>>(x);
    gram_kernel<<<dim3(NPAIR, Bc), 256>>>(t, out);
    tot_kernel<<<Bc, 256>>>();
    center_kernel<<<dim3(64, Bc), 256>>>(out);
}